// round 1
// baseline (speedup 1.0000x reference)
#include <cuda_runtime.h>

#define B_   4
#define C_   64
#define H_   128
#define W_   128
#define O_   64
#define KK   3
#define K2C  9
#define OFFC 18   // 2*K*K offset channels
#define HW   (H_*W_)

// Scratch: offset feature map (output of the first conv) and transposed DCN weights.
__device__ float g_offset[B_ * OFFC * HW];      // [b][oc][h][w]
__device__ float g_wt[K2C * C_ * O_];           // [k2][c][o]

// ---------------------------------------------------------------------------
// Kernel 1: offset conv (3x3, 64 -> 18, pad 1). One thread per output pixel,
// all 18 output channels accumulated in registers. Weights in shared, padded
// to 20 floats per (c,k) so the inner read is 5x LDS.128.
// ---------------------------------------------------------------------------
__global__ void __launch_bounds__(256) offset_conv_kernel(
    const float* __restrict__ x,
    const float* __restrict__ w_off,
    const float* __restrict__ b_off)
{
    __shared__ float ws[C_ * K2C * 20];   // [c][k][20], 45 KB

    const int t = threadIdx.x;
    for (int i = t; i < C_ * K2C * 20; i += 256) {
        int rem = i % 20;
        int ck  = i / 20;                 // c*9 + k
        float v = 0.f;
        if (rem < OFFC) {
            int c = ck / K2C, k = ck % K2C;
            v = w_off[(rem * C_ + c) * K2C + k];  // w_off[oc][c][kh][kw]
        }
        ws[i] = v;
    }
    __syncthreads();

    const int wo = t & 127;
    const int ho = blockIdx.x * 2 + (t >> 7);
    const int b  = blockIdx.y;

    float acc[20];
#pragma unroll
    for (int i = 0; i < 20; i++) acc[i] = 0.f;

    // tap validity / base offsets (independent of channel)
    bool valid[K2C];
    int  off[K2C];
#pragma unroll
    for (int k = 0; k < K2C; k++) {
        int dy = k / 3 - 1, dx = k % 3 - 1;
        int yy = ho + dy, xx = wo + dx;
        valid[k] = (yy >= 0) & (yy < H_) & (xx >= 0) & (xx < W_);
        off[k]   = yy * W_ + xx;
    }

    const float* xb = x + (size_t)b * C_ * HW;
    for (int c = 0; c < C_; c++) {
        const float* xc = xb + c * HW;
        float xv[K2C];
#pragma unroll
        for (int k = 0; k < K2C; k++)
            xv[k] = valid[k] ? __ldg(xc + off[k]) : 0.f;
#pragma unroll
        for (int k = 0; k < K2C; k++) {
            const float4* wp = (const float4*)(ws + (c * K2C + k) * 20);
            float xk = xv[k];
#pragma unroll
            for (int q = 0; q < 5; q++) {
                float4 w4 = wp[q];
                acc[q * 4 + 0] += xk * w4.x;
                acc[q * 4 + 1] += xk * w4.y;
                acc[q * 4 + 2] += xk * w4.z;
                acc[q * 4 + 3] += xk * w4.w;
            }
        }
    }

    float* op = g_offset + ((size_t)(b * OFFC) * H_ + ho) * W_ + wo;
#pragma unroll
    for (int oc = 0; oc < OFFC; oc++)
        op[(size_t)oc * HW] = acc[oc] + __ldg(b_off + oc);
}

// ---------------------------------------------------------------------------
// Kernel 2: transpose DCN weights [O][C][K2] -> [K2][C][O] so the main kernel
// reads each k2 slice fully coalesced.
// ---------------------------------------------------------------------------
__global__ void transpose_w_kernel(const float* __restrict__ w_dcn)
{
    int i = blockIdx.x * 256 + threadIdx.x;
    if (i < O_ * C_ * K2C) {
        int o  = i / (C_ * K2C);
        int r  = i % (C_ * K2C);
        int c  = r / K2C;
        int k2 = r % K2C;
        g_wt[(k2 * C_ + c) * O_ + o] = w_dcn[i];
    }
}

// ---------------------------------------------------------------------------
// Kernel 3: deformable conv. Block = 32 contiguous-wo pixels of one (b, ho).
// Per k2: cooperatively bilinear-sample [C=64 x 32 pixels] into smem and load
// the 16 KB weight slice, then implicit GEMM: each thread owns 8 output
// channels (warp id) for 1 pixel (lane id).
// ---------------------------------------------------------------------------
__global__ void __launch_bounds__(256) deform_kernel(
    const float* __restrict__ x,
    const float* __restrict__ b_dcn,
    float* __restrict__ out)
{
    __shared__ float ws[C_ * O_];      // 16 KB: [c][o] for current k2
    __shared__ float smp[C_ * 32];     // 8 KB:  [c][pixel]
    __shared__ int   m_y0[K2C][32];
    __shared__ int   m_x0[K2C][32];
    __shared__ float m_wy[K2C][32];
    __shared__ float m_wx[K2C][32];

    const int t    = threadIdx.x;
    const int lane = t & 31;
    const int warp = t >> 5;
    const int wo0  = blockIdx.x * 32;
    const int ho   = blockIdx.y;
    const int b    = blockIdx.z;

    // Precompute sampling metadata for all 9 kernel taps x 32 pixels.
    for (int e = t; e < K2C * 32; e += 256) {
        int k2 = e >> 5, pj = e & 31;
        int wo = wo0 + pj;
        const float* ob = g_offset + ((size_t)(b * OFFC + 2 * k2) * H_ + ho) * W_ + wo;
        float oy = ob[0];
        float ox = ob[HW];                         // channel 2*k2+1
        float py = (float)(ho - 1 + k2 / 3) + oy;
        float px = (float)(wo - 1 + k2 % 3) + ox;
        float y0f = floorf(py), x0f = floorf(px);
        m_y0[k2][pj] = (int)y0f;
        m_x0[k2][pj] = (int)x0f;
        m_wy[k2][pj] = py - y0f;
        m_wx[k2][pj] = px - x0f;
    }

    float acc[8];
#pragma unroll
    for (int i = 0; i < 8; i++) acc[i] = 0.f;

    const float* xb = x + (size_t)b * C_ * HW;

    __syncthreads();

    for (int k2 = 0; k2 < K2C; k2++) {
        // ---- phase 1: sampling (each thread: its pixel, 8 channels) + w slice load
        {
            int   y0 = m_y0[k2][lane];
            int   x0 = m_x0[k2][lane];
            float wy = m_wy[k2][lane];
            float wx = m_wx[k2][lane];
            bool vy0 = (y0 >= 0) & (y0 < H_);
            bool vy1 = (y0 + 1 >= 0) & (y0 + 1 < H_);
            bool vx0 = (x0 >= 0) & (x0 < W_);
            bool vx1 = (x0 + 1 >= 0) & (x0 + 1 < W_);
            bool p00 = vy0 & vx0, p01 = vy0 & vx1, p10 = vy1 & vx0, p11 = vy1 & vx1;
            float w00 = (1.f - wy) * (1.f - wx);
            float w01 = (1.f - wy) * wx;
            float w10 = wy * (1.f - wx);
            float w11 = wy * wx;
            int base = y0 * W_ + x0;

#pragma unroll
            for (int j = 0; j < 8; j++) {
                int c = warp * 8 + j;
                const float* xc = xb + c * HW;
                float v00 = p00 ? __ldg(xc + base)          : 0.f;
                float v01 = p01 ? __ldg(xc + base + 1)      : 0.f;
                float v10 = p10 ? __ldg(xc + base + W_)     : 0.f;
                float v11 = p11 ? __ldg(xc + base + W_ + 1) : 0.f;
                smp[c * 32 + lane] = v00 * w00 + v01 * w01 + v10 * w10 + v11 * w11;
            }

            // coalesced 16 KB weight slice load: 4 float4 per thread
            const float4* src = (const float4*)(g_wt + k2 * C_ * O_);
            float4* dst = (float4*)ws;
#pragma unroll
            for (int q = 0; q < 4; q++)
                dst[t + q * 256] = src[t + q * 256];
        }
        __syncthreads();

        // ---- phase 2: implicit GEMM over c
        {
            const int ob = warp * 8;
#pragma unroll 4
            for (int c = 0; c < C_; c++) {
                float s = smp[c * 32 + lane];
                const float4* wp = (const float4*)(ws + c * O_ + ob);
                float4 w0 = wp[0], w1 = wp[1];
                acc[0] += s * w0.x; acc[1] += s * w0.y;
                acc[2] += s * w0.z; acc[3] += s * w0.w;
                acc[4] += s * w1.x; acc[5] += s * w1.y;
                acc[6] += s * w1.z; acc[7] += s * w1.w;
            }
        }
        __syncthreads();
    }

    // ---- epilogue
    const int wo = wo0 + lane;
#pragma unroll
    for (int i = 0; i < 8; i++) {
        int o = warp * 8 + i;
        out[(((size_t)b * O_ + o) * H_ + ho) * W_ + wo] = acc[i] + __ldg(b_dcn + o);
    }
}

// ---------------------------------------------------------------------------
extern "C" void kernel_launch(void* const* d_in, const int* in_sizes, int n_in,
                              void* d_out, int out_size)
{
    const float* x     = (const float*)d_in[0];
    const float* w_off = (const float*)d_in[1];
    const float* b_off = (const float*)d_in[2];
    const float* w_dcn = (const float*)d_in[3];
    const float* b_dcn = (const float*)d_in[4];
    float* out = (float*)d_out;

    offset_conv_kernel<<<dim3(H_ / 2, B_), 256>>>(x, w_off, b_off);
    transpose_w_kernel<<<(O_ * C_ * K2C + 255) / 256, 256>>>(w_dcn);
    deform_kernel<<<dim3(W_ / 32, H_, B_), 256>>>(x, b_dcn, out);
}

// round 2
// speedup vs baseline: 1.1888x; 1.1888x over previous
#include <cuda_runtime.h>

#define B_   4
#define C_   64
#define H_   128
#define W_   128
#define O_   64
#define K2C  9
#define OFFC 18
#define HW   (H_*W_)

typedef unsigned long long ull;

__device__ float g_offset[B_ * OFFC * HW];   // [b][oc][h][w]
__device__ float g_wt[K2C * C_ * O_];        // [k2][c][o]

// ---- packed fp32x2 helpers (Blackwell) -------------------------------------
__device__ __forceinline__ void ffma2(ull& d, ull a, ull b) {
    asm("fma.rn.f32x2 %0, %1, %2, %0;" : "+l"(d) : "l"(a), "l"(b));
}
__device__ __forceinline__ ull pack2(float s) {
    ull r;
    asm("mov.b64 %0, {%1, %1};" : "=l"(r) : "f"(s));
    return r;
}
__device__ __forceinline__ float2 unpack2(ull v) {
    float2 f;
    asm("mov.b64 {%0, %1}, %2;" : "=f"(f.x), "=f"(f.y) : "l"(v));
    return f;
}

// ---------------------------------------------------------------------------
// Kernel 1: offset conv (3x3, 64 -> 18, pad 1). One thread per output pixel,
// 18 output channels in 9 f32x2 accumulators (padded to 10). Block = 1 row.
// ---------------------------------------------------------------------------
__global__ void __launch_bounds__(128) offset_conv_kernel(
    const float* __restrict__ x,
    const float* __restrict__ w_off,
    const float* __restrict__ b_off)
{
    __shared__ float ws[C_ * K2C * 20];   // [c][k][20 padded], 45 KB

    const int t = threadIdx.x;
    for (int i = t; i < C_ * K2C * 20; i += 128) {
        int rem = i % 20;
        int ck  = i / 20;
        float v = 0.f;
        if (rem < OFFC) {
            int c = ck / K2C, k = ck % K2C;
            v = w_off[(rem * C_ + c) * K2C + k];
        }
        ws[i] = v;
    }
    __syncthreads();

    const int wo = t;
    const int ho = blockIdx.x;
    const int b  = blockIdx.y;

    ull acc[10];
#pragma unroll
    for (int i = 0; i < 10; i++) acc[i] = 0ull;

    bool valid[K2C];
    int  off[K2C];
#pragma unroll
    for (int k = 0; k < K2C; k++) {
        int yy = ho + k / 3 - 1, xx = wo + k % 3 - 1;
        valid[k] = (yy >= 0) & (yy < H_) & (xx >= 0) & (xx < W_);
        off[k]   = yy * W_ + xx;
    }

    const float* xb = x + (size_t)b * C_ * HW;
    for (int c = 0; c < C_; c++) {
        const float* xc = xb + c * HW;
        float xv[K2C];
#pragma unroll
        for (int k = 0; k < K2C; k++)
            xv[k] = valid[k] ? __ldg(xc + off[k]) : 0.f;
#pragma unroll
        for (int k = 0; k < K2C; k++) {
            ull s2 = pack2(xv[k]);
            const ulonglong2* wp = (const ulonglong2*)(ws + (c * K2C + k) * 20);
#pragma unroll
            for (int q = 0; q < 5; q++) {
                ulonglong2 w = wp[q];
                ffma2(acc[2 * q + 0], s2, w.x);
                ffma2(acc[2 * q + 1], s2, w.y);
            }
        }
    }

    float* op = g_offset + ((size_t)(b * OFFC) * H_ + ho) * W_ + wo;
#pragma unroll
    for (int j = 0; j < 9; j++) {
        float2 v = unpack2(acc[j]);
        op[(size_t)(2 * j + 0) * HW] = v.x + __ldg(b_off + 2 * j + 0);
        op[(size_t)(2 * j + 1) * HW] = v.y + __ldg(b_off + 2 * j + 1);
    }
}

// ---------------------------------------------------------------------------
// Kernel 2: transpose DCN weights [O][C][K2] -> [K2][C][O].
// ---------------------------------------------------------------------------
__global__ void transpose_w_kernel(const float* __restrict__ w_dcn)
{
    int i = blockIdx.x * 256 + threadIdx.x;
    if (i < O_ * C_ * K2C) {
        int o  = i / (C_ * K2C);
        int r  = i % (C_ * K2C);
        int c  = r / K2C;
        int k2 = r % K2C;
        g_wt[(k2 * C_ + c) * O_ + o] = w_dcn[i];
    }
}

// ---------------------------------------------------------------------------
// Kernel 3: deformable conv. Block = 64 contiguous-wo pixels of one (b, ho).
// Thread (warp w, lane l): pixels {l, l+32}, output channels 8w..8w+7 as
// 4 f32x2 pairs per pixel. Per k2: cooperative bilinear sampling into
// smp[c][px] + coalesced weight slice load, then f32x2 implicit GEMM.
// ---------------------------------------------------------------------------
__global__ void __launch_bounds__(256) deform_kernel(
    const float* __restrict__ x,
    const float* __restrict__ b_dcn,
    float* __restrict__ out)
{
    __shared__ float  ws[C_ * O_];        // 16 KB [c][o]
    __shared__ float  smp[C_][64];        // 16 KB [c][px]
    __shared__ float2 meta[K2C][64];      // 4.5 KB (py, px)

    const int t    = threadIdx.x;
    const int lane = t & 31;
    const int warp = t >> 5;
    const int wo0  = blockIdx.x * 64;
    const int ho   = blockIdx.y;
    const int b    = blockIdx.z;

    // sampling positions for 9 taps x 64 pixels
    for (int e = t; e < K2C * 64; e += 256) {
        int k2 = e >> 6, p = e & 63;
        int wo = wo0 + p;
        const float* ob = g_offset + ((size_t)(b * OFFC + 2 * k2) * H_ + ho) * W_ + wo;
        float oy = ob[0];
        float ox = ob[HW];
        meta[k2][p] = make_float2((float)(ho - 1 + k2 / 3) + oy,
                                  (float)(wo - 1 + k2 % 3) + ox);
    }

    ull acc[2][4];
#pragma unroll
    for (int i = 0; i < 2; i++)
#pragma unroll
        for (int j = 0; j < 4; j++) acc[i][j] = 0ull;

    const float* xb = x + (size_t)b * C_ * HW;
    __syncthreads();

    for (int k2 = 0; k2 < K2C; k2++) {
        // weight slice [c][o] for this tap: 16 KB coalesced
        {
            const float4* src = (const float4*)(g_wt + k2 * C_ * O_);
            float4* dst = (float4*)ws;
#pragma unroll
            for (int q = 0; q < 4; q++)
                dst[t + q * 256] = src[t + q * 256];
        }

        // bilinear sampling: 2 pixels x 8 channels per thread
#pragma unroll
        for (int i = 0; i < 2; i++) {
            int p = lane + 32 * i;
            float2 m = meta[k2][p];
            float y0f = floorf(m.x), x0f = floorf(m.y);
            float wy = m.x - y0f, wx = m.y - x0f;
            int y0 = (int)y0f, x0 = (int)x0f;
            bool vy0 = (y0 >= 0) & (y0 < H_);
            bool vy1 = (y0 >= -1) & (y0 < H_ - 1);
            bool vx0 = (x0 >= 0) & (x0 < W_);
            bool vx1 = (x0 >= -1) & (x0 < W_ - 1);
            bool p00 = vy0 & vx0, p01 = vy0 & vx1, p10 = vy1 & vx0, p11 = vy1 & vx1;
            float w00 = (1.f - wy) * (1.f - wx);
            float w01 = (1.f - wy) * wx;
            float w10 = wy * (1.f - wx);
            float w11 = wy * wx;
            int base = y0 * W_ + x0;
#pragma unroll
            for (int j = 0; j < 8; j++) {
                int c = warp * 8 + j;
                const float* xc = xb + c * HW;
                float v00 = p00 ? __ldg(xc + base)          : 0.f;
                float v01 = p01 ? __ldg(xc + base + 1)      : 0.f;
                float v10 = p10 ? __ldg(xc + base + W_)     : 0.f;
                float v11 = p11 ? __ldg(xc + base + W_ + 1) : 0.f;
                smp[c][p] = v00 * w00 + v01 * w01 + v10 * w10 + v11 * w11;
            }
        }
        __syncthreads();

        // f32x2 implicit GEMM over c
        {
            const int ob = warp * 8;
#pragma unroll 4
            for (int c = 0; c < C_; c++) {
                ulonglong2 wA = *(const ulonglong2*)(ws + c * O_ + ob);
                ulonglong2 wB = *(const ulonglong2*)(ws + c * O_ + ob + 4);
#pragma unroll
                for (int i = 0; i < 2; i++) {
                    ull s2 = pack2(smp[c][lane + 32 * i]);
                    ffma2(acc[i][0], s2, wA.x);
                    ffma2(acc[i][1], s2, wA.y);
                    ffma2(acc[i][2], s2, wB.x);
                    ffma2(acc[i][3], s2, wB.y);
                }
            }
        }
        __syncthreads();
    }

    // epilogue
#pragma unroll
    for (int i = 0; i < 2; i++) {
        int wo = wo0 + lane + 32 * i;
#pragma unroll
        for (int j = 0; j < 4; j++) {
            float2 v = unpack2(acc[i][j]);
            int o = warp * 8 + 2 * j;
            out[(((size_t)b * O_ + o)     * H_ + ho) * W_ + wo] = v.x + __ldg(b_dcn + o);
            out[(((size_t)b * O_ + o + 1) * H_ + ho) * W_ + wo] = v.y + __ldg(b_dcn + o + 1);
        }
    }
}

// ---------------------------------------------------------------------------
extern "C" void kernel_launch(void* const* d_in, const int* in_sizes, int n_in,
                              void* d_out, int out_size)
{
    const float* x     = (const float*)d_in[0];
    const float* w_off = (const float*)d_in[1];
    const float* b_off = (const float*)d_in[2];
    const float* w_dcn = (const float*)d_in[3];
    const float* b_dcn = (const float*)d_in[4];
    float* out = (float*)d_out;

    offset_conv_kernel<<<dim3(H_, B_), 128>>>(x, w_off, b_off);
    transpose_w_kernel<<<(O_ * C_ * K2C + 255) / 256, 256>>>(w_dcn);
    deform_kernel<<<dim3(W_ / 64, H_, B_), 256>>>(x, b_dcn, out);
}

// round 3
// speedup vs baseline: 1.2539x; 1.0548x over previous
#include <cuda_runtime.h>

#define B_   4
#define C_   64
#define H_   128
#define W_   128
#define O_   64
#define K2C  9
#define OFFC 18
#define HW   (H_*W_)

typedef unsigned long long ull;

__device__ float g_offset[B_ * OFFC * HW];   // [b][oc][h][w]
__device__ float g_wt[K2C * C_ * O_];        // [k2][c][o]

// ---- packed fp32x2 helpers (Blackwell) -------------------------------------
__device__ __forceinline__ void ffma2(ull& d, ull a, ull b) {
    asm("fma.rn.f32x2 %0, %1, %2, %0;" : "+l"(d) : "l"(a), "l"(b));
}
__device__ __forceinline__ ull pack2(float s) {
    ull r;
    asm("mov.b64 %0, {%1, %1};" : "=l"(r) : "f"(s));
    return r;
}
__device__ __forceinline__ float2 unpack2(ull v) {
    float2 f;
    asm("mov.b64 {%0, %1}, %2;" : "=f"(f.x), "=f"(f.y) : "l"(v));
    return f;
}

// ---------------------------------------------------------------------------
// Kernel 1: offset conv (3x3, 64 -> 18, pad 1). 256 threads = 128 px x 2
// channel-halves; each half accumulates 32 channels into 9 f32x2 accs (pad 10),
// then halves are combined through smem. Doubles resident threads vs 1px/thr.
// ---------------------------------------------------------------------------
__global__ void __launch_bounds__(256) offset_conv_kernel(
    const float* __restrict__ x,
    const float* __restrict__ w_off,
    const float* __restrict__ b_off)
{
    __shared__ float ws[C_ * K2C * 20];   // [c][k][20 padded], 45 KB
    __shared__ ull   red[9][128];         // partial sums from upper half, 9.2 KB

    const int t = threadIdx.x;
    for (int i = t; i < C_ * K2C * 20; i += 256) {
        int rem = i % 20;
        int ck  = i / 20;
        float v = 0.f;
        if (rem < OFFC) {
            int c = ck / K2C, k = ck % K2C;
            v = w_off[(rem * C_ + c) * K2C + k];
        }
        ws[i] = v;
    }
    __syncthreads();

    const int wo   = t & 127;
    const int half = t >> 7;          // 0 or 1: channel range 32*half..+32
    const int ho   = blockIdx.x;
    const int b    = blockIdx.y;

    ull acc[10];
#pragma unroll
    for (int i = 0; i < 10; i++) acc[i] = 0ull;

    bool valid[K2C];
    int  off[K2C];
#pragma unroll
    for (int k = 0; k < K2C; k++) {
        int yy = ho + k / 3 - 1, xx = wo + k % 3 - 1;
        valid[k] = (yy >= 0) & (yy < H_) & (xx >= 0) & (xx < W_);
        off[k]   = yy * W_ + xx;
    }

    const float* xb = x + (size_t)b * C_ * HW;
    const int c0 = half * 32;
    for (int c = c0; c < c0 + 32; c++) {
        const float* xc = xb + c * HW;
        float xv[K2C];
#pragma unroll
        for (int k = 0; k < K2C; k++)
            xv[k] = valid[k] ? __ldg(xc + off[k]) : 0.f;
#pragma unroll
        for (int k = 0; k < K2C; k++) {
            ull s2 = pack2(xv[k]);
            const ulonglong2* wp = (const ulonglong2*)(ws + (c * K2C + k) * 20);
#pragma unroll
            for (int q = 0; q < 5; q++) {
                ulonglong2 w = wp[q];
                ffma2(acc[2 * q + 0], s2, w.x);
                ffma2(acc[2 * q + 1], s2, w.y);
            }
        }
    }

    if (half == 1) {
#pragma unroll
        for (int j = 0; j < 9; j++) red[j][wo] = acc[j];
    }
    __syncthreads();
    if (half == 0) {
        float* op = g_offset + ((size_t)(b * OFFC) * H_ + ho) * W_ + wo;
#pragma unroll
        for (int j = 0; j < 9; j++) {
            float2 a = unpack2(acc[j]);
            float2 p = unpack2(red[j][wo]);
            op[(size_t)(2 * j + 0) * HW] = a.x + p.x + __ldg(b_off + 2 * j + 0);
            op[(size_t)(2 * j + 1) * HW] = a.y + p.y + __ldg(b_off + 2 * j + 1);
        }
    }
}

// ---------------------------------------------------------------------------
// Kernel 2: transpose DCN weights [O][C][K2] -> [K2][C][O].
// ---------------------------------------------------------------------------
__global__ void transpose_w_kernel(const float* __restrict__ w_dcn)
{
    int i = blockIdx.x * 256 + threadIdx.x;
    if (i < O_ * C_ * K2C) {
        int o  = i / (C_ * K2C);
        int r  = i % (C_ * K2C);
        int c  = r / K2C;
        int k2 = r % K2C;
        g_wt[(k2 * C_ + c) * O_ + o] = w_dcn[i];
    }
}

// ---------------------------------------------------------------------------
// Kernel 3: deformable conv. Block = one output row (128 px), 256 threads.
// 8 warps = 4 oc-groups (16 oc each) x 2 px-groups (64 px each).
// Thread tile: 2 px x 16 oc = 16 f32x2 accumulators. Per c per warp the GEMM
// does 4 broadcast LDS.128 (weights) + 2 scalar LDS.32 (samples) feeding
// 16 FFMA2 (ratio 2.67:1 vs 2:1 before).
// ---------------------------------------------------------------------------
__global__ void __launch_bounds__(256) deform_kernel(
    const float* __restrict__ x,
    const float* __restrict__ b_dcn,
    float* __restrict__ out)
{
    __shared__ float  ws[C_ * O_];        // 16 KB [c][o]
    __shared__ float  smp[C_][128];       // 32 KB [c][px]
    __shared__ float2 meta[K2C][128];     // 9 KB (py, px)

    const int t    = threadIdx.x;
    const int lane = t & 31;
    const int warp = t >> 5;
    const int ocg  = warp & 3;            // oc base = 16*ocg
    const int pxg  = warp >> 2;           // px half: 0 or 1
    const int px0  = lane + 64 * pxg;     // this thread's pixels: px0, px0+32
    const int ho   = blockIdx.x;
    const int b    = blockIdx.y;

    // sampling positions for 9 taps x 128 pixels
    for (int e = t; e < K2C * 128; e += 256) {
        int k2 = e >> 7, p = e & 127;
        const float* ob = g_offset + ((size_t)(b * OFFC + 2 * k2) * H_ + ho) * W_ + p;
        float oy = ob[0];
        float ox = ob[HW];
        meta[k2][p] = make_float2((float)(ho - 1 + k2 / 3) + oy,
                                  (float)(p  - 1 + k2 % 3) + ox);
    }

    ull acc[2][8];
#pragma unroll
    for (int i = 0; i < 2; i++)
#pragma unroll
        for (int j = 0; j < 8; j++) acc[i][j] = 0ull;

    const float* xb = x + (size_t)b * C_ * HW;
    __syncthreads();

    for (int k2 = 0; k2 < K2C; k2++) {
        // stage weight slice [c][o] for this tap: 16 KB coalesced
        {
            const float4* src = (const float4*)(g_wt + k2 * C_ * O_);
            float4* dst = (float4*)ws;
#pragma unroll
            for (int q = 0; q < 4; q++)
                dst[t + q * 256] = src[t + q * 256];
        }

        // bilinear sampling: this thread covers its 2 px x 16 channels
#pragma unroll
        for (int i = 0; i < 2; i++) {
            int p = px0 + 32 * i;
            float2 m = meta[k2][p];
            float y0f = floorf(m.x), x0f = floorf(m.y);
            float wy = m.x - y0f, wx = m.y - x0f;
            int y0 = (int)y0f, x0 = (int)x0f;
            bool vy0 = (y0 >= 0) & (y0 < H_);
            bool vy1 = (y0 >= -1) & (y0 < H_ - 1);
            bool vx0 = (x0 >= 0) & (x0 < W_);
            bool vx1 = (x0 >= -1) & (x0 < W_ - 1);
            bool p00 = vy0 & vx0, p01 = vy0 & vx1, p10 = vy1 & vx0, p11 = vy1 & vx1;
            float w00 = (1.f - wy) * (1.f - wx);
            float w01 = (1.f - wy) * wx;
            float w10 = wy * (1.f - wx);
            float w11 = wy * wx;
            int base = y0 * W_ + x0;
#pragma unroll
            for (int j = 0; j < 16; j++) {
                int c = ocg * 16 + j;
                const float* xc = xb + c * HW;
                float v00 = p00 ? __ldg(xc + base)          : 0.f;
                float v01 = p01 ? __ldg(xc + base + 1)      : 0.f;
                float v10 = p10 ? __ldg(xc + base + W_)     : 0.f;
                float v11 = p11 ? __ldg(xc + base + W_ + 1) : 0.f;
                smp[c][p] = v00 * w00 + v01 * w01 + v10 * w10 + v11 * w11;
            }
        }
        __syncthreads();

        // f32x2 implicit GEMM over c: 2 px x 16 oc per thread
        {
            const int ob = ocg * 16;
#pragma unroll 4
            for (int c = 0; c < C_; c++) {
                const ulonglong2* wp = (const ulonglong2*)(ws + c * O_ + ob);
                ulonglong2 wA = wp[0], wB = wp[1], wC = wp[2], wD = wp[3];
                ull s0 = pack2(smp[c][px0]);
                ull s1 = pack2(smp[c][px0 + 32]);
                ffma2(acc[0][0], s0, wA.x); ffma2(acc[0][1], s0, wA.y);
                ffma2(acc[0][2], s0, wB.x); ffma2(acc[0][3], s0, wB.y);
                ffma2(acc[0][4], s0, wC.x); ffma2(acc[0][5], s0, wC.y);
                ffma2(acc[0][6], s0, wD.x); ffma2(acc[0][7], s0, wD.y);
                ffma2(acc[1][0], s1, wA.x); ffma2(acc[1][1], s1, wA.y);
                ffma2(acc[1][2], s1, wB.x); ffma2(acc[1][3], s1, wB.y);
                ffma2(acc[1][4], s1, wC.x); ffma2(acc[1][5], s1, wC.y);
                ffma2(acc[1][6], s1, wD.x); ffma2(acc[1][7], s1, wD.y);
            }
        }
        __syncthreads();
    }

    // epilogue
#pragma unroll
    for (int i = 0; i < 2; i++) {
        int wo = px0 + 32 * i;
#pragma unroll
        for (int j = 0; j < 8; j++) {
            float2 v = unpack2(acc[i][j]);
            int o = ocg * 16 + 2 * j;
            out[(((size_t)b * O_ + o)     * H_ + ho) * W_ + wo] = v.x + __ldg(b_dcn + o);
            out[(((size_t)b * O_ + o + 1) * H_ + ho) * W_ + wo] = v.y + __ldg(b_dcn + o + 1);
        }
    }
}

// ---------------------------------------------------------------------------
extern "C" void kernel_launch(void* const* d_in, const int* in_sizes, int n_in,
                              void* d_out, int out_size)
{
    const float* x     = (const float*)d_in[0];
    const float* w_off = (const float*)d_in[1];
    const float* b_off = (const float*)d_in[2];
    const float* w_dcn = (const float*)d_in[3];
    const float* b_dcn = (const float*)d_in[4];
    float* out = (float*)d_out;

    offset_conv_kernel<<<dim3(H_, B_), 256>>>(x, w_off, b_off);
    transpose_w_kernel<<<(O_ * C_ * K2C + 255) / 256, 256>>>(w_dcn);
    deform_kernel<<<dim3(H_, B_), 256>>>(x, b_dcn, out);
}

// round 4
// speedup vs baseline: 1.3064x; 1.0418x over previous
#include <cuda_runtime.h>

#define B_   4
#define C_   64
#define H_   128
#define W_   128
#define O_   64
#define K2C  9
#define OFFC 18
#define HW   (H_*W_)

typedef unsigned long long ull;

__device__ float g_offset[B_ * OFFC * HW];   // [b][oc][h][w]
__device__ float g_wt[K2C * C_ * O_];        // [k2][c][o]

// ---- packed fp32x2 helpers (Blackwell) -------------------------------------
__device__ __forceinline__ void ffma2(ull& d, ull a, ull b) {
    asm("fma.rn.f32x2 %0, %1, %2, %0;" : "+l"(d) : "l"(a), "l"(b));
}
__device__ __forceinline__ ull pack2(float s) {
    ull r;
    asm("mov.b64 %0, {%1, %1};" : "=l"(r) : "f"(s));
    return r;
}
__device__ __forceinline__ float2 unpack2(ull v) {
    float2 f;
    asm("mov.b64 {%0, %1}, %2;" : "=f"(f.x), "=f"(f.y) : "l"(v));
    return f;
}

// ---------------------------------------------------------------------------
// Kernel 1: offset conv (3x3, 64 -> 18, pad 1). 512 threads = 128 px x 4
// channel-chunks (16 ch each). Each chunk accumulates into 9 f32x2 accs
// (padded to 10); chunks 1-3 dump to smem, chunk 0 reduces and stores.
// ---------------------------------------------------------------------------
__global__ void __launch_bounds__(512) offset_conv_kernel(
    const float* __restrict__ x,
    const float* __restrict__ w_off,
    const float* __restrict__ b_off)
{
    __shared__ float ws[C_ * K2C * 20];   // 45 KB [c][k][20 padded]
    __shared__ ull   red[3][9][128];      // 27 KB partials from chunks 1..3

    const int t = threadIdx.x;
    for (int i = t; i < C_ * K2C * 20; i += 512) {
        int rem = i % 20;
        int ck  = i / 20;
        float v = 0.f;
        if (rem < OFFC) {
            int c = ck / K2C, k = ck % K2C;
            v = w_off[(rem * C_ + c) * K2C + k];
        }
        ws[i] = v;
    }
    __syncthreads();

    const int wo    = t & 127;
    const int chunk = t >> 7;             // 0..3 -> channels 16*chunk..+16
    const int ho    = blockIdx.x;
    const int b     = blockIdx.y;

    ull acc[10];
#pragma unroll
    for (int i = 0; i < 10; i++) acc[i] = 0ull;

    bool valid[K2C];
    int  off[K2C];
#pragma unroll
    for (int k = 0; k < K2C; k++) {
        int yy = ho + k / 3 - 1, xx = wo + k % 3 - 1;
        valid[k] = (yy >= 0) & (yy < H_) & (xx >= 0) & (xx < W_);
        off[k]   = yy * W_ + xx;
    }

    const float* xb = x + (size_t)b * C_ * HW;
    const int c0 = chunk * 16;
    for (int c = c0; c < c0 + 16; c++) {
        const float* xc = xb + c * HW;
        float xv[K2C];
#pragma unroll
        for (int k = 0; k < K2C; k++)
            xv[k] = valid[k] ? __ldg(xc + off[k]) : 0.f;
#pragma unroll
        for (int k = 0; k < K2C; k++) {
            ull s2 = pack2(xv[k]);
            const ulonglong2* wp = (const ulonglong2*)(ws + (c * K2C + k) * 20);
#pragma unroll
            for (int q = 0; q < 5; q++) {
                ulonglong2 w = wp[q];
                ffma2(acc[2 * q + 0], s2, w.x);
                ffma2(acc[2 * q + 1], s2, w.y);
            }
        }
    }

    if (chunk != 0) {
#pragma unroll
        for (int j = 0; j < 9; j++) red[chunk - 1][j][wo] = acc[j];
    }
    __syncthreads();
    if (chunk == 0) {
        float* op = g_offset + ((size_t)(b * OFFC) * H_ + ho) * W_ + wo;
#pragma unroll
        for (int j = 0; j < 9; j++) {
            float2 a  = unpack2(acc[j]);
            float2 p1 = unpack2(red[0][j][wo]);
            float2 p2 = unpack2(red[1][j][wo]);
            float2 p3 = unpack2(red[2][j][wo]);
            op[(size_t)(2 * j + 0) * HW] =
                (a.x + p1.x) + (p2.x + p3.x) + __ldg(b_off + 2 * j + 0);
            op[(size_t)(2 * j + 1) * HW] =
                (a.y + p1.y) + (p2.y + p3.y) + __ldg(b_off + 2 * j + 1);
        }
    }
}

// ---------------------------------------------------------------------------
// Kernel 2: transpose DCN weights [O][C][K2] -> [K2][C][O].
// ---------------------------------------------------------------------------
__global__ void transpose_w_kernel(const float* __restrict__ w_dcn)
{
    int i = blockIdx.x * 256 + threadIdx.x;
    if (i < O_ * C_ * K2C) {
        int o  = i / (C_ * K2C);
        int r  = i % (C_ * K2C);
        int c  = r / K2C;
        int k2 = r % K2C;
        g_wt[(k2 * C_ + c) * O_ + o] = w_dcn[i];
    }
}

// ---------------------------------------------------------------------------
// Kernel 3: deformable conv. Block = 256 px (2 rows), 256 threads.
// 8 warps = 4 oc-groups (16 oc) x 2 px-groups (128 px). Thread tile:
// 4 px x 16 oc = 32 f32x2 accumulators. Samples staged in 32-channel halves
// (smp 32x256) so the GEMM does 4 LDS.128 + 4 LDS.32 per 32 FFMA2.
// ---------------------------------------------------------------------------
__global__ void __launch_bounds__(256, 2) deform_kernel(
    const float* __restrict__ x,
    const float* __restrict__ b_dcn,
    float* __restrict__ out)
{
    __shared__ float  ws[C_ * O_];        // 16 KB [c][o]
    __shared__ float  smp[32][256];       // 32 KB [c_half][px]
    __shared__ float2 meta[K2C][256];     // 18 KB (py, px)

    const int t    = threadIdx.x;
    const int lane = t & 31;
    const int warp = t >> 5;
    const int ocg  = warp & 3;            // oc base = 16*ocg
    const int pxg  = warp >> 2;           // px half: 0 or 1 (128 px each)
    const int pbase = 128 * pxg + lane;   // thread pixels: pbase + 32*i
    const int ho0  = blockIdx.x * 2;
    const int b    = blockIdx.y;

    // sampling positions for 9 taps x 256 pixels
    for (int e = t; e < K2C * 256; e += 256) {
        int k2 = e >> 8, p = e & 255;
        int ho = ho0 + (p >> 7), wo = p & 127;
        const float* ob = g_offset + ((size_t)(b * OFFC + 2 * k2) * H_ + ho) * W_ + wo;
        float oy = ob[0];
        float ox = ob[HW];
        meta[k2][p] = make_float2((float)(ho - 1 + k2 / 3) + oy,
                                  (float)(wo - 1 + k2 % 3) + ox);
    }

    ull acc[4][8];
#pragma unroll
    for (int i = 0; i < 4; i++)
#pragma unroll
        for (int j = 0; j < 8; j++) acc[i][j] = 0ull;

    const float* xb = x + (size_t)b * C_ * HW;
    __syncthreads();

    for (int k2 = 0; k2 < K2C; k2++) {
        // stage weight slice [c][o] for this tap (prev GEMM done via last sync)
        {
            const float4* src = (const float4*)(g_wt + k2 * C_ * O_);
            float4* dst = (float4*)ws;
#pragma unroll
            for (int q = 0; q < 4; q++)
                dst[t + q * 256] = src[t + q * 256];
        }

#pragma unroll
        for (int ch = 0; ch < 2; ch++) {
            // bilinear sampling: this thread covers 4 px x 8 channels
#pragma unroll
            for (int i = 0; i < 4; i++) {
                int p = pbase + 32 * i;
                float2 m = meta[k2][p];
                float y0f = floorf(m.x), x0f = floorf(m.y);
                float wy = m.x - y0f, wx = m.y - x0f;
                int y0 = (int)y0f, x0 = (int)x0f;
                bool vy0 = (y0 >= 0) & (y0 < H_);
                bool vy1 = (y0 >= -1) & (y0 < H_ - 1);
                bool vx0 = (x0 >= 0) & (x0 < W_);
                bool vx1 = (x0 >= -1) & (x0 < W_ - 1);
                bool p00 = vy0 & vx0, p01 = vy0 & vx1;
                bool p10 = vy1 & vx0, p11 = vy1 & vx1;
                float w00 = (1.f - wy) * (1.f - wx);
                float w01 = (1.f - wy) * wx;
                float w10 = wy * (1.f - wx);
                float w11 = wy * wx;
                int base = y0 * W_ + x0;
#pragma unroll
                for (int j = 0; j < 8; j++) {
                    int c = ch * 32 + ocg * 8 + j;
                    const float* xc = xb + c * HW;
                    float v00 = p00 ? __ldg(xc + base)          : 0.f;
                    float v01 = p01 ? __ldg(xc + base + 1)      : 0.f;
                    float v10 = p10 ? __ldg(xc + base + W_)     : 0.f;
                    float v11 = p11 ? __ldg(xc + base + W_ + 1) : 0.f;
                    smp[c & 31][p] = v00 * w00 + v01 * w01 + v10 * w10 + v11 * w11;
                }
            }
            __syncthreads();

            // f32x2 implicit GEMM over this 32-channel half
            {
                const int ob = ocg * 16;
#pragma unroll 4
                for (int cl = 0; cl < 32; cl++) {
                    int c = ch * 32 + cl;
                    const ulonglong2* wp = (const ulonglong2*)(ws + c * O_ + ob);
                    ulonglong2 wA = wp[0], wB = wp[1], wC = wp[2], wD = wp[3];
#pragma unroll
                    for (int i = 0; i < 4; i++) {
                        ull s = pack2(smp[cl][pbase + 32 * i]);
                        ffma2(acc[i][0], s, wA.x); ffma2(acc[i][1], s, wA.y);
                        ffma2(acc[i][2], s, wB.x); ffma2(acc[i][3], s, wB.y);
                        ffma2(acc[i][4], s, wC.x); ffma2(acc[i][5], s, wC.y);
                        ffma2(acc[i][6], s, wD.x); ffma2(acc[i][7], s, wD.y);
                    }
                }
            }
            __syncthreads();
        }
    }

    // epilogue
#pragma unroll
    for (int i = 0; i < 4; i++) {
        int p  = pbase + 32 * i;
        int ho = ho0 + (p >> 7);
        int wo = p & 127;
#pragma unroll
        for (int j = 0; j < 8; j++) {
            float2 v = unpack2(acc[i][j]);
            int o = ocg * 16 + 2 * j;
            out[(((size_t)b * O_ + o)     * H_ + ho) * W_ + wo] = v.x + __ldg(b_dcn + o);
            out[(((size_t)b * O_ + o + 1) * H_ + ho) * W_ + wo] = v.y + __ldg(b_dcn + o + 1);
        }
    }
}

// ---------------------------------------------------------------------------
extern "C" void kernel_launch(void* const* d_in, const int* in_sizes, int n_in,
                              void* d_out, int out_size)
{
    const float* x     = (const float*)d_in[0];
    const float* w_off = (const float*)d_in[1];
    const float* b_off = (const float*)d_in[2];
    const float* w_dcn = (const float*)d_in[3];
    const float* b_dcn = (const float*)d_in[4];
    float* out = (float*)d_out;

    offset_conv_kernel<<<dim3(H_, B_), 512>>>(x, w_off, b_off);
    transpose_w_kernel<<<(O_ * C_ * K2C + 255) / 256, 256>>>(w_dcn);
    deform_kernel<<<dim3(H_ / 2, B_), 256>>>(x, b_dcn, out);
}

// round 5
// speedup vs baseline: 1.4320x; 1.0962x over previous
#include <cuda_runtime.h>

#define B_   4
#define C_   64
#define H_   128
#define W_   128
#define O_   64
#define K2C  9
#define OFFC 18
#define HW   (H_*W_)

typedef unsigned long long ull;

__device__ float g_offset[B_ * OFFC * HW];   // [b][oc][h][w]
__device__ float g_wt[K2C * C_ * O_];        // [k2][c][o]

// ---- packed fp32x2 helpers (Blackwell) -------------------------------------
__device__ __forceinline__ void ffma2(ull& d, ull a, ull b) {
    asm("fma.rn.f32x2 %0, %1, %2, %0;" : "+l"(d) : "l"(a), "l"(b));
}
__device__ __forceinline__ ull pack2(float s) {
    ull r;
    asm("mov.b64 %0, {%1, %1};" : "=l"(r) : "f"(s));
    return r;
}
__device__ __forceinline__ float2 unpack2(ull v) {
    float2 f;
    asm("mov.b64 {%0, %1}, %2;" : "=f"(f.x), "=f"(f.y) : "l"(v));
    return f;
}

// ---------------------------------------------------------------------------
// Kernel 1: offset conv (3x3, 64 -> 18, pad 1).
// 256 threads = 64 pixel-PAIRS x 4 channel-chunks (16 ch each).
// Each thread computes 2 adjacent pixels: the 3x3 taps of the pair span 4
// contiguous floats per row, loaded as 3 aligned LDG.64 (halves LDG/px) and
// the weight LDS.128s are shared across both pixels (halves LDS/px).
// ---------------------------------------------------------------------------
__global__ void __launch_bounds__(256, 2) offset_conv_kernel(
    const float* __restrict__ x,
    const float* __restrict__ w_off,
    const float* __restrict__ b_off)
{
    __shared__ float ws[C_ * K2C * 20];   // 45 KB [c][k][20 padded]
    __shared__ ull   red[3][9][128];      // 27 KB partials, indexed by pixel

    const int t = threadIdx.x;
    for (int i = t; i < C_ * K2C * 20; i += 256) {
        int rem = i % 20;
        int ck  = i / 20;
        float v = 0.f;
        if (rem < OFFC) {
            int c = ck / K2C, k = ck % K2C;
            v = w_off[(rem * C_ + c) * K2C + k];
        }
        ws[i] = v;
    }
    __syncthreads();

    const int pp    = t & 63;             // pixel pair id
    const int chunk = t >> 6;             // 0..3 -> channels 16*chunk..+16
    const int wo0   = pp * 2;             // pixels wo0, wo0+1
    const int ho    = blockIdx.x;
    const int b     = blockIdx.y;

    ull acc0[10], acc1[10];
#pragma unroll
    for (int i = 0; i < 10; i++) { acc0[i] = 0ull; acc1[i] = 0ull; }

    bool rv[3]; int rbase[3];
#pragma unroll
    for (int r = 0; r < 3; r++) {
        int yy = ho + r - 1;
        rv[r] = (yy >= 0) & (yy < H_);
        rbase[r] = yy * W_;
    }
    const bool s0v = (wo0 >= 2);
    const bool s2v = (wo0 <= W_ - 4);

    const float* xb = x + (size_t)b * C_ * HW;
    const int c0 = chunk * 16;
    for (int c = c0; c < c0 + 16; c++) {
        const float* xc = xb + c * HW;
        float f[3][6];
#pragma unroll
        for (int r = 0; r < 3; r++) {
            float2 a = make_float2(0.f, 0.f);
            float2 m = make_float2(0.f, 0.f);
            float2 e = make_float2(0.f, 0.f);
            if (rv[r]) {
                if (s0v) a = __ldg((const float2*)(xc + rbase[r] + wo0 - 2));
                m = __ldg((const float2*)(xc + rbase[r] + wo0));
                if (s2v) e = __ldg((const float2*)(xc + rbase[r] + wo0 + 2));
            }
            f[r][0] = a.x; f[r][1] = a.y;
            f[r][2] = m.x; f[r][3] = m.y;
            f[r][4] = e.x; f[r][5] = e.y;
        }
#pragma unroll
        for (int k = 0; k < K2C; k++) {
            int r = k / 3, kw = k % 3;
            ull s0 = pack2(f[r][1 + kw]);
            ull s1 = pack2(f[r][2 + kw]);
            const ulonglong2* wp = (const ulonglong2*)(ws + (c * K2C + k) * 20);
#pragma unroll
            for (int q = 0; q < 5; q++) {
                ulonglong2 w = wp[q];
                ffma2(acc0[2 * q + 0], s0, w.x);
                ffma2(acc0[2 * q + 1], s0, w.y);
                ffma2(acc1[2 * q + 0], s1, w.x);
                ffma2(acc1[2 * q + 1], s1, w.y);
            }
        }
    }

    if (chunk != 0) {
#pragma unroll
        for (int j = 0; j < 9; j++) {
            red[chunk - 1][j][wo0]     = acc0[j];
            red[chunk - 1][j][wo0 + 1] = acc1[j];
        }
    }
    __syncthreads();
    if (chunk == 0) {
        float* op = g_offset + ((size_t)(b * OFFC) * H_ + ho) * W_ + wo0;
#pragma unroll
        for (int j = 0; j < 9; j++) {
            float2 a0 = unpack2(acc0[j]);
            float2 a1 = unpack2(acc1[j]);
            float2 p10 = unpack2(red[0][j][wo0]);
            float2 p11 = unpack2(red[0][j][wo0 + 1]);
            float2 p20 = unpack2(red[1][j][wo0]);
            float2 p21 = unpack2(red[1][j][wo0 + 1]);
            float2 p30 = unpack2(red[2][j][wo0]);
            float2 p31 = unpack2(red[2][j][wo0 + 1]);
            float bx = __ldg(b_off + 2 * j + 0);
            float by = __ldg(b_off + 2 * j + 1);
            op[(size_t)(2 * j + 0) * HW]     = (a0.x + p10.x) + (p20.x + p30.x) + bx;
            op[(size_t)(2 * j + 0) * HW + 1] = (a1.x + p11.x) + (p21.x + p31.x) + bx;
            op[(size_t)(2 * j + 1) * HW]     = (a0.y + p10.y) + (p20.y + p30.y) + by;
            op[(size_t)(2 * j + 1) * HW + 1] = (a1.y + p11.y) + (p21.y + p31.y) + by;
        }
    }
}

// ---------------------------------------------------------------------------
// Kernel 2: transpose DCN weights [O][C][K2] -> [K2][C][O].
// ---------------------------------------------------------------------------
__global__ void transpose_w_kernel(const float* __restrict__ w_dcn)
{
    int i = blockIdx.x * 256 + threadIdx.x;
    if (i < O_ * C_ * K2C) {
        int o  = i / (C_ * K2C);
        int r  = i % (C_ * K2C);
        int c  = r / K2C;
        int k2 = r % K2C;
        g_wt[(k2 * C_ + c) * O_ + o] = w_dcn[i];
    }
}

// ---------------------------------------------------------------------------
// Kernel 3: deformable conv, software-pipelined.
// Block = 256 px (2 rows), 256 threads; 8 warps = 4 oc-groups x 2 px-groups.
// Thread tile: 4 px x 16 oc (32 f32x2 accs). 18 pipeline iterations
// (9 taps x 2 channel-halves): sampling for iter i+1 (LDG-heavy) is issued
// before the GEMM of iter i (FFMA2-heavy), one sync per iteration, so the
// two pipes overlap across warps. Tap validity folded into bilinear weights.
// ---------------------------------------------------------------------------
__global__ void __launch_bounds__(256, 2) deform_kernel(
    const float* __restrict__ x,
    const float* __restrict__ b_dcn,
    float* __restrict__ out)
{
    __shared__ float ws[2][C_ * O_];      // 32 KB, double-buffered per k2
    __shared__ float smp[2][32][256];     // 64 KB, double-buffered per half

    const int t     = threadIdx.x;
    const int lane  = t & 31;
    const int warp  = t >> 5;
    const int ocg   = warp & 3;           // oc base = 16*ocg
    const int pxg   = warp >> 2;          // px half: 0 or 1 (128 px)
    const int pbase = 128 * pxg + lane;   // pixels: pbase + 32*i
    const int ho0   = blockIdx.x * 2;
    const int b     = blockIdx.y;

    const float* xb = x + (size_t)b * C_ * HW;

    // --- stage weight slice for tap k2 into ws[buf] (16 KB coalesced) ---
    auto stage_ws = [&](int wbuf, int k2) {
        const float4* src = (const float4*)(g_wt + k2 * C_ * O_);
        float4* dst = (float4*)ws[wbuf];
#pragma unroll
        for (int q = 0; q < 4; q++)
            dst[t + q * 256] = src[t + q * 256];
    };

    // --- bilinear sampling of (k2, channel-half ch) into smp[sbuf] ---
    auto sample = [&](int sbuf, int k2, int ch) {
#pragma unroll
        for (int i = 0; i < 4; i++) {
            int p  = pbase + 32 * i;
            int ho = ho0 + (p >> 7);
            int wo = p & 127;
            const float* ob =
                g_offset + ((size_t)(b * OFFC + 2 * k2) * H_ + ho) * W_ + wo;
            float oy = ob[0];
            float ox = ob[HW];
            float py = (float)(ho - 1 + k2 / 3) + oy;
            float px = (float)(wo - 1 + k2 % 3) + ox;
            float y0f = floorf(py), x0f = floorf(px);
            float wy = py - y0f, wx = px - x0f;
            int y0 = (int)y0f, x0 = (int)x0f;
            // validity folded into weights; indices clamped
            float vy0 = ((y0 >= 0)  & (y0 < H_))      ? 1.f : 0.f;
            float vy1 = ((y0 >= -1) & (y0 < H_ - 1))  ? 1.f : 0.f;
            float vx0 = ((x0 >= 0)  & (x0 < W_))      ? 1.f : 0.f;
            float vx1 = ((x0 >= -1) & (x0 < W_ - 1))  ? 1.f : 0.f;
            float w00 = (1.f - wy) * (1.f - wx) * vy0 * vx0;
            float w01 = (1.f - wy) * wx         * vy0 * vx1;
            float w10 = wy * (1.f - wx)         * vy1 * vx0;
            float w11 = wy * wx                 * vy1 * vx1;
            int y0c = min(max(y0, 0), H_ - 1);
            int y1c = min(max(y0 + 1, 0), H_ - 1);
            int x0c = min(max(x0, 0), W_ - 1);
            int x1c = min(max(x0 + 1, 0), W_ - 1);
            int o00 = y0c * W_ + x0c;
            int o01 = y0c * W_ + x1c;
            int o10 = y1c * W_ + x0c;
            int o11 = y1c * W_ + x1c;
#pragma unroll
            for (int j = 0; j < 8; j++) {
                int cl = ocg * 8 + j;             // 0..31 within half
                const float* xc = xb + (ch * 32 + cl) * HW;
                float s = __ldg(xc + o00) * w00 + __ldg(xc + o01) * w01
                        + __ldg(xc + o10) * w10 + __ldg(xc + o11) * w11;
                smp[sbuf][cl][p] = s;
            }
        }
    };

    ull acc[4][8];
#pragma unroll
    for (int i = 0; i < 4; i++)
#pragma unroll
        for (int j = 0; j < 8; j++) acc[i][j] = 0ull;

    // prologue
    stage_ws(0, 0);
    sample(0, 0, 0);
    __syncthreads();

    for (int it = 0; it < 18; it++) {
        const int buf = it & 1;
        const int k2  = it >> 1;
        const int ch  = it & 1;

        // issue next iteration's memory work first (overlaps GEMM below)
        if (it < 17) {
            int nk2 = (it + 1) >> 1, nch = (it + 1) & 1;
            if (nch == 0) stage_ws(nk2 & 1, nk2);
            sample(buf ^ 1, nk2, nch);
        }

        // f32x2 implicit GEMM over this 32-channel half
        {
            const int ob = ocg * 16;
            const float* wsl = ws[k2 & 1] + ch * 32 * O_ + ob;
#pragma unroll 4
            for (int cl = 0; cl < 32; cl++) {
                const ulonglong2* wp = (const ulonglong2*)(wsl + cl * O_);
                ulonglong2 wA = wp[0], wB = wp[1], wC = wp[2], wD = wp[3];
#pragma unroll
                for (int i = 0; i < 4; i++) {
                    ull s = pack2(smp[buf][cl][pbase + 32 * i]);
                    ffma2(acc[i][0], s, wA.x); ffma2(acc[i][1], s, wA.y);
                    ffma2(acc[i][2], s, wB.x); ffma2(acc[i][3], s, wB.y);
                    ffma2(acc[i][4], s, wC.x); ffma2(acc[i][5], s, wC.y);
                    ffma2(acc[i][6], s, wD.x); ffma2(acc[i][7], s, wD.y);
                }
            }
        }
        __syncthreads();
    }

    // epilogue
#pragma unroll
    for (int i = 0; i < 4; i++) {
        int p  = pbase + 32 * i;
        int ho = ho0 + (p >> 7);
        int wo = p & 127;
#pragma unroll
        for (int j = 0; j < 8; j++) {
            float2 v = unpack2(acc[i][j]);
            int o = ocg * 16 + 2 * j;
            out[(((size_t)b * O_ + o)     * H_ + ho) * W_ + wo] = v.x + __ldg(b_dcn + o);
            out[(((size_t)b * O_ + o + 1) * H_ + ho) * W_ + wo] = v.y + __ldg(b_dcn + o + 1);
        }
    }
}

// ---------------------------------------------------------------------------
extern "C" void kernel_launch(void* const* d_in, const int* in_sizes, int n_in,
                              void* d_out, int out_size)
{
    const float* x     = (const float*)d_in[0];
    const float* w_off = (const float*)d_in[1];
    const float* b_off = (const float*)d_in[2];
    const float* w_dcn = (const float*)d_in[3];
    const float* b_dcn = (const float*)d_in[4];
    float* out = (float*)d_out;

    offset_conv_kernel<<<dim3(H_, B_), 256>>>(x, w_off, b_off);
    transpose_w_kernel<<<(O_ * C_ * K2C + 255) / 256, 256>>>(w_dcn);
    deform_kernel<<<dim3(H_ / 2, B_), 256>>>(x, b_dcn, out);
}